// round 9
// baseline (speedup 1.0000x reference)
#include <cuda_runtime.h>
#include <cuda_bf16.h>
#include <math.h>
#include <stdint.h>

// ---------------- problem constants ----------------
constexpr int CC   = 128;
constexpr int CT   = 16;
constexpr int CH   = 56;
constexpr int CW   = 56;
constexpr int NTOK = 196;
constexpr int NWIN = 1024;
constexpr int MTOK = NWIN * NTOK;     // 200704
constexpr int SPT  = CT * CH * CW;    // 50176
constexpr int HW   = CH * CW;         // 3136

// ---------------- scratch ----------------
__device__ __nv_bfloat16 g_qkv[(size_t)MTOK * 384];
__device__ float         g_y1 [(size_t)MTOK * 128];
__device__ __nv_bfloat16 g_wqkvT[384 * 128];
__device__ __nv_bfloat16 g_wpT  [128 * 128];
__device__ __nv_bfloat16 g_w1T  [512 * 128];
__device__ __nv_bfloat16 g_w2T  [128 * 512];

__device__ __forceinline__ void row_to_bsp(int R, int &b, int &sp) {
    int w = R / NTOK, n = R - w * NTOK;
    b = w >> 8;
    int rw = w & 255;
    int it = rw >> 6, ih = (rw >> 3) & 7, iw = rw & 7;
    int tt = n / 49;
    int rn = n - tt * 49;
    int hh = rn / 7, ww = rn - hh * 7;
    sp = (it * 4 + tt) * HW + (ih * 7 + hh) * CW + (iw * 7 + ww);
}

__device__ __forceinline__ void mma4(float* d, uint32_t a0, uint32_t a1, uint32_t a2, uint32_t a3,
                                     uint32_t b0, uint32_t b1) {
    asm volatile(
        "mma.sync.aligned.m16n8k16.row.col.f32.bf16.bf16.f32 "
        "{%0,%1,%2,%3},{%4,%5,%6,%7},{%8,%9},{%0,%1,%2,%3};"
        : "+f"(d[0]), "+f"(d[1]), "+f"(d[2]), "+f"(d[3])
        : "r"(a0), "r"(a1), "r"(a2), "r"(a3), "r"(b0), "r"(b1));
}

__device__ __forceinline__ void ldsm4(uint32_t* r, uint32_t saddr) {
    asm volatile("ldmatrix.sync.aligned.m8n8.x4.shared.b16 {%0,%1,%2,%3}, [%4];"
        : "=r"(r[0]), "=r"(r[1]), "=r"(r[2]), "=r"(r[3]) : "r"(saddr));
}

__device__ __forceinline__ uint32_t s2u(const void* p) {
    return (uint32_t)__cvta_generic_to_shared(p);
}

__device__ __forceinline__ uint32_t packbf(float x, float y) {
    __nv_bfloat162 t = __floats2bfloat162_rn(x, y);
    return *reinterpret_cast<uint32_t*>(&t);
}
__device__ __forceinline__ void st_bf2(__nv_bfloat16* p, float x, float y) {
    __nv_bfloat162 t = __floats2bfloat162_rn(x, y);
    *reinterpret_cast<__nv_bfloat162*>(p) = t;
}

__device__ __forceinline__ void cp16(uint32_t s, const void* g) {
    asm volatile("cp.async.cg.shared.global [%0], [%1], 16;" :: "r"(s), "l"(g));
}
#define CP_COMMIT() asm volatile("cp.async.commit_group;" ::: "memory")
#define CP_WAIT0()  asm volatile("cp.async.wait_group 0;" ::: "memory")

constexpr int PA = 136;

// =====================================================================
// K0: weight transpose + bf16 convert
// =====================================================================
__global__ void kprep(const float* __restrict__ qkvw, const float* __restrict__ pw,
                      const float* __restrict__ w1,   const float* __restrict__ w2)
{
    int i = blockIdx.x * 256 + threadIdx.x;
    if (i < 49152) { int n = i >> 7, k = i & 127; g_wqkvT[n * 128 + k] = __float2bfloat16(qkvw[k * 384 + n]); return; }
    i -= 49152;
    if (i < 16384) { int n = i >> 7, k = i & 127; g_wpT[n * 128 + k] = __float2bfloat16(pw[k * 128 + n]); return; }
    i -= 16384;
    if (i < 65536) { int n = i >> 7, k = i & 127; g_w1T[n * 128 + k] = __float2bfloat16(w1[k * 512 + n]); return; }
    i -= 65536;
    if (i < 65536) { int n = i >> 9, k = i & 511; g_w2T[n * 512 + k] = __float2bfloat16(w2[k * 128 + n]); return; }
}

// =====================================================================
// K1: BN + window gather + qkv GEMM  (R7 passing version)
// =====================================================================
__global__ __launch_bounds__(256) void k1_qkv(
    const float* __restrict__ x,
    const float* __restrict__ bng, const float* __restrict__ bnb,
    const float* __restrict__ bnm, const float* __restrict__ bnv,
    const float* __restrict__ bq)
{
    extern __shared__ unsigned char shraw[];
    __nv_bfloat16* As = (__nv_bfloat16*)shraw;        // [128][PA]
    __nv_bfloat16* Bs = As + 128 * PA;                // [64][PA]
    __shared__ float sc[128], sf[128];
    int tid = threadIdx.x;
    if (tid < 128) {
        float s = bng[tid] * rsqrtf(bnv[tid] + 1e-5f);
        sc[tid] = s;
        sf[tid] = bnb[tid] - bnm[tid] * s;
    }
    __syncthreads();

    int r = tid & 127, cs = tid >> 7;
    int R0 = blockIdx.x * 128;
    {
        int b, sp; row_to_bsp(R0 + r, b, sp);
        const float* xp = x + (size_t)b * 128 * SPT + sp + (size_t)cs * 64 * SPT;
        #pragma unroll 8
        for (int j = 0; j < 64; j++) {
            int c = cs * 64 + j;
            As[r * PA + c] = __float2bfloat16(xp[(size_t)j * SPT] * sc[c] + sf[c]);
        }
    }

    int w = tid >> 5, l = tid & 31;
    int mw = (w >> 1) * 32, nw = (w & 1) * 32;
    int kq = (l & 3) * 2;

    uint32_t aA = s2u(As) + (((mw + (l & 15)) * PA + (l >> 4) * 8) << 1);
    uint32_t aB = s2u(Bs) + (((nw + (l & 7) + ((l >> 4) << 3)) * PA + ((l >> 3) & 1) * 8) << 1);

    for (int nt = 0; nt < 6; nt++) {
        __syncthreads();
        for (int i = tid; i < 64 * 16; i += 256) {
            int n = i >> 4, seg = i & 15;
            *(uint4*)&Bs[n * PA + seg * 8] = *(const uint4*)&g_wqkvT[(nt * 64 + n) * 128 + seg * 8];
        }
        __syncthreads();
        float acc[2][4][4];
        #pragma unroll
        for (int a = 0; a < 2; a++)
            #pragma unroll
            for (int bb = 0; bb < 4; bb++)
                acc[a][bb][0] = acc[a][bb][1] = acc[a][bb][2] = acc[a][bb][3] = 0.f;

        #pragma unroll
        for (int k0 = 0; k0 < 128; k0 += 16) {
            uint32_t a0[4], a1[4], b0[4], b1[4];
            ldsm4(a0, aA + k0 * 2);
            ldsm4(a1, aA + 16 * PA * 2 + k0 * 2);
            ldsm4(b0, aB + k0 * 2);
            ldsm4(b1, aB + 16 * PA * 2 + k0 * 2);
            mma4(acc[0][0], a0[0], a0[1], a0[2], a0[3], b0[0], b0[1]);
            mma4(acc[0][1], a0[0], a0[1], a0[2], a0[3], b0[2], b0[3]);
            mma4(acc[0][2], a0[0], a0[1], a0[2], a0[3], b1[0], b1[1]);
            mma4(acc[0][3], a0[0], a0[1], a0[2], a0[3], b1[2], b1[3]);
            mma4(acc[1][0], a1[0], a1[1], a1[2], a1[3], b0[0], b0[1]);
            mma4(acc[1][1], a1[0], a1[1], a1[2], a1[3], b0[2], b0[3]);
            mma4(acc[1][2], a1[0], a1[1], a1[2], a1[3], b1[0], b1[1]);
            mma4(acc[1][3], a1[0], a1[1], a1[2], a1[3], b1[2], b1[3]);
        }
        #pragma unroll
        for (int ntb = 0; ntb < 4; ntb++) {
            int cg = nt * 64 + nw + ntb * 8 + kq;
            float bx = bq[cg], by = bq[cg + 1];
            #pragma unroll
            for (int mt = 0; mt < 2; mt++) {
                int r0 = R0 + mw + mt * 16 + (l >> 2);
                st_bf2(&g_qkv[(size_t)r0 * 384 + cg],       acc[mt][ntb][0] + bx, acc[mt][ntb][1] + by);
                st_bf2(&g_qkv[(size_t)(r0 + 8) * 384 + cg], acc[mt][ntb][2] + bx, acc[mt][ntb][3] + by);
            }
        }
    }
}

// =====================================================================
// K2': per-window attention (4 heads) + proj + residual -> y1 (R7 passing)
// =====================================================================
constexpr int PQ2 = 40;
constexpr int PVT = 216;
constexpr int PO  = 136;
constexpr int OFF_KS = 208 * PQ2;
constexpr int OFF_VT = OFF_KS + 208 * PQ2;
constexpr int OFF_O  = OFF_VT + 32 * PVT;
constexpr int SM2_ELEMS = OFF_O + 208 * PO;

__global__ __launch_bounds__(256) void k2_attnproj(
    const float* __restrict__ x, const float* __restrict__ bp)
{
    extern __shared__ unsigned char shraw[];
    __nv_bfloat16* sm = (__nv_bfloat16*)shraw;
    __nv_bfloat16* Qs = sm;
    __nv_bfloat16* Ks = sm + OFF_KS;
    __nv_bfloat16* Vt = sm + OFF_VT;
    __nv_bfloat16* Os = sm + OFF_O;

    int tid = threadIdx.x, l = tid & 31, wid = tid >> 5;
    int win = blockIdx.x;
    int qbase = win * NTOK;
    int kq = (l & 3) * 2;
    const float scale = 0.17677669529663687f;

    for (int i = tid; i < 12 * PO; i += 256) Os[196 * PO + i] = __float2bfloat16(0.f);

    uint32_t aKbase = s2u(Ks) + ((((l & 7) + ((l >> 4) << 3)) * PQ2 + ((l >> 3) & 1) * 8) << 1);
    uint32_t aVbase = s2u(Vt) + ((((l & 7) + ((l >> 4) << 3)) * PVT + ((l >> 3) & 1) * 8) << 1);

    for (int h = 0; h < 4; h++) {
        __syncthreads();
        int coff = h * 32;
        for (int i = tid; i < 208 * 32; i += 256) {
            int n = i >> 5, d = i & 31;
            __nv_bfloat16 qv, kv, vv;
            if (n < NTOK) {
                const __nv_bfloat16* p = &g_qkv[(size_t)(qbase + n) * 384 + coff + d];
                qv = p[0]; kv = p[128]; vv = p[256];
            } else {
                qv = __float2bfloat16(0.f); kv = qv; vv = qv;
            }
            Qs[n * PQ2 + d] = qv;
            Ks[n * PQ2 + d] = kv;
            Vt[d * PVT + n] = vv;
        }
        __syncthreads();

        for (int u = wid; u < 13; u += 8) {
            int m0 = u * 16;
            float S[26][4];
            #pragma unroll
            for (int t = 0; t < 26; t++) S[t][0] = S[t][1] = S[t][2] = S[t][3] = 0.f;

            uint32_t aQ = s2u(Qs) + (((m0 + (l & 15)) * PQ2 + (l >> 4) * 8) << 1);
            #pragma unroll
            for (int k0 = 0; k0 < 32; k0 += 16) {
                uint32_t aq[4];
                ldsm4(aq, aQ + k0 * 2);
                #pragma unroll
                for (int p = 0; p < 13; p++) {
                    uint32_t bk[4];
                    ldsm4(bk, aKbase + (p * 16 * PQ2 + k0) * 2);
                    mma4(S[2 * p],     aq[0], aq[1], aq[2], aq[3], bk[0], bk[1]);
                    mma4(S[2 * p + 1], aq[0], aq[1], aq[2], aq[3], bk[2], bk[3]);
                }
            }

            float mx0 = -1e30f, mx1 = -1e30f;
            #pragma unroll
            for (int t = 0; t < 26; t++) {
                int c = t * 8 + kq;
                if (c < NTOK)     { mx0 = fmaxf(mx0, S[t][0]); mx1 = fmaxf(mx1, S[t][2]); }
                if (c + 1 < NTOK) { mx0 = fmaxf(mx0, S[t][1]); mx1 = fmaxf(mx1, S[t][3]); }
            }
            mx0 = fmaxf(mx0, __shfl_xor_sync(0xffffffffu, mx0, 1));
            mx0 = fmaxf(mx0, __shfl_xor_sync(0xffffffffu, mx0, 2));
            mx1 = fmaxf(mx1, __shfl_xor_sync(0xffffffffu, mx1, 1));
            mx1 = fmaxf(mx1, __shfl_xor_sync(0xffffffffu, mx1, 2));

            float s0 = 0.f, s1 = 0.f;
            #pragma unroll
            for (int t = 0; t < 26; t++) {
                int c = t * 8 + kq;
                if (c < NTOK)     { S[t][0] = __expf(scale * (S[t][0] - mx0)); s0 += S[t][0];
                                    S[t][2] = __expf(scale * (S[t][2] - mx1)); s1 += S[t][2]; }
                else              { S[t][0] = 0.f; S[t][2] = 0.f; }
                if (c + 1 < NTOK) { S[t][1] = __expf(scale * (S[t][1] - mx0)); s0 += S[t][1];
                                    S[t][3] = __expf(scale * (S[t][3] - mx1)); s1 += S[t][3]; }
                else              { S[t][1] = 0.f; S[t][3] = 0.f; }
            }
            s0 += __shfl_xor_sync(0xffffffffu, s0, 1);
            s0 += __shfl_xor_sync(0xffffffffu, s0, 2);
            s1 += __shfl_xor_sync(0xffffffffu, s1, 1);
            s1 += __shfl_xor_sync(0xffffffffu, s1, 2);
            float i0 = 1.f / s0, i1 = 1.f / s1;
            #pragma unroll
            for (int t = 0; t < 26; t++) {
                S[t][0] *= i0; S[t][1] *= i0; S[t][2] *= i1; S[t][3] *= i1;
            }

            float O[4][4];
            #pragma unroll
            for (int nt = 0; nt < 4; nt++) O[nt][0] = O[nt][1] = O[nt][2] = O[nt][3] = 0.f;
            #pragma unroll
            for (int kt = 0; kt < 13; kt++) {
                uint32_t pa0 = packbf(S[2 * kt][0],     S[2 * kt][1]);
                uint32_t pa1 = packbf(S[2 * kt][2],     S[2 * kt][3]);
                uint32_t pa2 = packbf(S[2 * kt + 1][0], S[2 * kt + 1][1]);
                uint32_t pa3 = packbf(S[2 * kt + 1][2], S[2 * kt + 1][3]);
                #pragma unroll
                for (int p = 0; p < 2; p++) {
                    uint32_t bv[4];
                    ldsm4(bv, aVbase + (p * 16 * PVT + kt * 16) * 2);
                    mma4(O[2 * p],     pa0, pa1, pa2, pa3, bv[0], bv[1]);
                    mma4(O[2 * p + 1], pa0, pa1, pa2, pa3, bv[2], bv[3]);
                }
            }

            int qr0 = m0 + (l >> 2), qr1 = qr0 + 8;
            #pragma unroll
            for (int nt = 0; nt < 4; nt++) {
                int cd = coff + nt * 8 + kq;
                if (qr0 < NTOK) st_bf2(&Os[qr0 * PO + cd], O[nt][0], O[nt][1]);
                if (qr1 < NTOK) st_bf2(&Os[qr1 * PO + cd], O[nt][2], O[nt][3]);
            }
        }
    }

    // ---- proj phase ----
    __syncthreads();
    __nv_bfloat16* Bs = sm;
    for (int i = tid; i < 128 * 16; i += 256) {
        int n = i >> 4, seg = i & 15;
        *(uint4*)&Bs[n * PO + seg * 8] = *(const uint4*)&g_wpT[n * 128 + seg * 8];
    }
    __syncthreads();

    uint32_t aBp = s2u(Bs) + ((((l & 7) + ((l >> 4) << 3)) * PO + ((l >> 3) & 1) * 8) << 1);

    for (int u = wid; u < 13; u += 8) {
        int m0 = u * 16;
        float acc[16][4];
        #pragma unroll
        for (int t = 0; t < 16; t++) acc[t][0] = acc[t][1] = acc[t][2] = acc[t][3] = 0.f;
        uint32_t aO = s2u(Os) + (((m0 + (l & 15)) * PO + (l >> 4) * 8) << 1);
        #pragma unroll
        for (int k0 = 0; k0 < 128; k0 += 16) {
            uint32_t ao[4];
            ldsm4(ao, aO + k0 * 2);
            #pragma unroll
            for (int p = 0; p < 8; p++) {
                uint32_t bb[4];
                ldsm4(bb, aBp + (p * 16 * PO + k0) * 2);
                mma4(acc[2 * p],     ao[0], ao[1], ao[2], ao[3], bb[0], bb[1]);
                mma4(acc[2 * p + 1], ao[0], ao[1], ao[2], ao[3], bb[2], bb[3]);
            }
        }
        #pragma unroll
        for (int half = 0; half < 2; half++) {
            int row = m0 + (l >> 2) + half * 8;
            if (row < NTOK) {
                int b, sp; row_to_bsp(qbase + row, b, sp);
                size_t xb = (size_t)b * 128 * SPT + sp;
                size_t tok = (size_t)b * SPT + sp;
                #pragma unroll
                for (int ntb = 0; ntb < 16; ntb++) {
                    int cg = ntb * 8 + kq;
                    float2 o;
                    o.x = acc[ntb][half * 2 + 0] + bp[cg]     + x[xb + (size_t)cg * SPT];
                    o.y = acc[ntb][half * 2 + 1] + bp[cg + 1] + x[xb + (size_t)(cg + 1) * SPT];
                    *(float2*)&g_y1[tok * 128 + cg] = o;
                }
            }
        }
    }
}

// =====================================================================
// K4: 512 thr, 1 CTA/SM. LN + fc1 + GELU + fc2 + residual + transposed out.
// cp.async double-buffered weights: W1 in buf0, W2 in buf1 (fixed roles).
// smem: A @0 (34816), H @34816, W0 @69632, W1 @104448; total 139264.
// =====================================================================
constexpr int F4_H  = 128 * PA * 2;        // 34816
constexpr int F4_W0 = 2 * 128 * PA * 2;    // 69632
constexpr int F4_W1 = 3 * 128 * PA * 2;    // 104448
constexpr int F4_TOTAL = 4 * 128 * PA * 2; // 139264

__global__ __launch_bounds__(512, 1) void k4_ffn(
    const float* __restrict__ lng, const float* __restrict__ lnb,
    const float* __restrict__ b1,  const float* __restrict__ b2,
    float* __restrict__ out)
{
    extern __shared__ unsigned char shraw[];
    __nv_bfloat16* A  = (__nv_bfloat16*)shraw;
    __nv_bfloat16* H  = (__nv_bfloat16*)(shraw + F4_H);
    uint32_t sA  = s2u(shraw);
    uint32_t sH  = sA + F4_H;
    uint32_t sW0 = sA + F4_W0;
    uint32_t sW1 = sA + F4_W1;
    int tid = threadIdx.x, l = tid & 31, w = tid >> 5;
    int R0 = blockIdx.x * 128;

    // LN -> A (4 threads/row, 32 ch each)
    {
        int row = tid >> 2, seg = tid & 3;
        const float* src = &g_y1[(size_t)(R0 + row) * 128 + seg * 32];
        float s1 = 0.f, s2 = 0.f;
        #pragma unroll
        for (int j = 0; j < 32; j += 4) {
            float4 t = *(const float4*)&src[j];
            s1 += t.x + t.y + t.z + t.w;
            s2 += t.x * t.x + t.y * t.y + t.z * t.z + t.w * t.w;
        }
        s1 += __shfl_xor_sync(0xffffffffu, s1, 1);
        s1 += __shfl_xor_sync(0xffffffffu, s1, 2);
        s2 += __shfl_xor_sync(0xffffffffu, s2, 1);
        s2 += __shfl_xor_sync(0xffffffffu, s2, 2);
        float mean = s1 * (1.f / 128.f);
        float var  = s2 * (1.f / 128.f) - mean * mean;
        float rstd = rsqrtf(var + 1e-5f);
        #pragma unroll
        for (int j = 0; j < 32; j += 2) {
            int c = seg * 32 + j;
            float v0 = (src[j]     - mean) * rstd * lng[c]     + lnb[c];
            float v1 = (src[j + 1] - mean) * rstd * lng[c + 1] + lnb[c + 1];
            *(uint32_t*)&A[row * PA + c] = packbf(v0, v1);
        }
    }

    // prefetch W1 chunk 0 -> W0
    {
        #pragma unroll
        for (int ii = 0; ii < 4; ii++) {
            int i = tid + ii * 512;
            int n = i >> 4, seg = i & 15;
            cp16(sW0 + (uint32_t)(n * PA + seg * 8) * 2, &g_w1T[(size_t)n * 128 + seg * 8]);
        }
        CP_COMMIT();
    }

    // warp tiling: 4m x 4n, each warp 32 rows x 32 cols
    int wm = (w & 3), wn = (w >> 2);
    int mwr = wm * 32, nwc = wn * 32;
    int kq = (l & 3) * 2;
    uint32_t aA = sA + (((mwr + (l & 15)) * PA + (l >> 4) * 8) << 1);
    uint32_t aH = sH + (((mwr + (l & 15)) * PA + (l >> 4) * 8) << 1);
    uint32_t bOff = ((uint32_t)((nwc + (l & 7) + ((l >> 4) << 3)) * PA + ((l >> 3) & 1) * 8)) << 1;

    float acc2[2][4][4];
    #pragma unroll
    for (int a = 0; a < 2; a++)
        #pragma unroll
        for (int bb = 0; bb < 4; bb++)
            acc2[a][bb][0] = acc2[a][bb][1] = acc2[a][bb][2] = acc2[a][bb][3] = 0.f;

    for (int kc = 0; kc < 4; kc++) {
        // W1(kc) ready; also covers A/H visibility
        CP_WAIT0();
        __syncthreads();

        // issue W2(kc) -> W1 buf
        #pragma unroll
        for (int ii = 0; ii < 4; ii++) {
            int i = tid + ii * 512;
            int n = i >> 4, seg = i & 15;
            cp16(sW1 + (uint32_t)(n * PA + seg * 8) * 2, &g_w2T[(size_t)n * 512 + kc * 128 + seg * 8]);
        }
        CP_COMMIT();

        // fc1: A x W0 -> acc -> GELU -> H
        {
            float acc[2][4][4];
            #pragma unroll
            for (int a = 0; a < 2; a++)
                #pragma unroll
                for (int bb = 0; bb < 4; bb++)
                    acc[a][bb][0] = acc[a][bb][1] = acc[a][bb][2] = acc[a][bb][3] = 0.f;

            #pragma unroll
            for (int k0 = 0; k0 < 128; k0 += 16) {
                uint32_t a0[4], a1[4], b0[4], b1[4];
                ldsm4(a0, aA + k0 * 2);
                ldsm4(a1, aA + 16 * PA * 2 + k0 * 2);
                ldsm4(b0, sW0 + bOff + k0 * 2);
                ldsm4(b1, sW0 + bOff + 16 * PA * 2 + k0 * 2);
                mma4(acc[0][0], a0[0], a0[1], a0[2], a0[3], b0[0], b0[1]);
                mma4(acc[0][1], a0[0], a0[1], a0[2], a0[3], b0[2], b0[3]);
                mma4(acc[0][2], a0[0], a0[1], a0[2], a0[3], b1[0], b1[1]);
                mma4(acc[0][3], a0[0], a0[1], a0[2], a0[3], b1[2], b1[3]);
                mma4(acc[1][0], a1[0], a1[1], a1[2], a1[3], b0[0], b0[1]);
                mma4(acc[1][1], a1[0], a1[1], a1[2], a1[3], b0[2], b0[3]);
                mma4(acc[1][2], a1[0], a1[1], a1[2], a1[3], b1[0], b1[1]);
                mma4(acc[1][3], a1[0], a1[1], a1[2], a1[3], b1[2], b1[3]);
            }
            #pragma unroll
            for (int ntb = 0; ntb < 4; ntb++) {
                int cl = nwc + ntb * 8 + kq;
                float bx = b1[kc * 128 + cl], by = b1[kc * 128 + cl + 1];
                #pragma unroll
                for (int mt = 0; mt < 2; mt++) {
                    #pragma unroll
                    for (int half = 0; half < 2; half++) {
                        int row = mwr + mt * 16 + (l >> 2) + half * 8;
                        float h0 = acc[mt][ntb][half * 2 + 0] + bx;
                        float h1 = acc[mt][ntb][half * 2 + 1] + by;
                        float g0 = 0.5f * h0 * (1.f + erff(h0 * 0.70710678118654752f));
                        float g1 = 0.5f * h1 * (1.f + erff(h1 * 0.70710678118654752f));
                        st_bf2(&H[row * PA + cl], g0, g1);
                    }
                }
            }
        }

        // wait W2(kc) landed (this thread), then barrier: H + W2 visible, W0 free
        CP_WAIT0();
        __syncthreads();

        // issue W1(kc+1) -> W0 buf
        if (kc < 3) {
            #pragma unroll
            for (int ii = 0; ii < 4; ii++) {
                int i = tid + ii * 512;
                int n = i >> 4, seg = i & 15;
                cp16(sW0 + (uint32_t)(n * PA + seg * 8) * 2,
                     &g_w1T[(size_t)((kc + 1) * 128 + n) * 128 + seg * 8]);
            }
            CP_COMMIT();
        }

        // fc2: H x W1buf -> acc2 accumulate
        #pragma unroll
        for (int k0 = 0; k0 < 128; k0 += 16) {
            uint32_t a0[4], a1[4], b0[4], b1[4];
            ldsm4(a0, aH + k0 * 2);
            ldsm4(a1, aH + 16 * PA * 2 + k0 * 2);
            ldsm4(b0, sW1 + bOff + k0 * 2);
            ldsm4(b1, sW1 + bOff + 16 * PA * 2 + k0 * 2);
            mma4(acc2[0][0], a0[0], a0[1], a0[2], a0[3], b0[0], b0[1]);
            mma4(acc2[0][1], a0[0], a0[1], a0[2], a0[3], b0[2], b0[3]);
            mma4(acc2[0][2], a0[0], a0[1], a0[2], a0[3], b1[0], b1[1]);
            mma4(acc2[0][3], a0[0], a0[1], a0[2], a0[3], b1[2], b1[3]);
            mma4(acc2[1][0], a1[0], a1[1], a1[2], a1[3], b0[0], b0[1]);
            mma4(acc2[1][1], a1[0], a1[1], a1[2], a1[3], b0[2], b0[3]);
            mma4(acc2[1][2], a1[0], a1[1], a1[2], a1[3], b1[0], b1[1]);
            mma4(acc2[1][3], a1[0], a1[1], a1[2], a1[3], b1[2], b1[3]);
        }
    }

    __syncthreads();   // all fc2 reads done; A/H free for Cs overlay
    float* Cs = (float*)shraw;   // [128][133] = 68096 B
    #pragma unroll
    for (int mt = 0; mt < 2; mt++) {
        #pragma unroll
        for (int half = 0; half < 2; half++) {
            int row = mwr + mt * 16 + (l >> 2) + half * 8;
            #pragma unroll
            for (int ntb = 0; ntb < 4; ntb++) {
                int c = nwc + ntb * 8 + kq;
                float2 yv = *(const float2*)&g_y1[(size_t)(R0 + row) * 128 + c];
                Cs[row * 133 + c]     = acc2[mt][ntb][half * 2 + 0] + b2[c]     + yv.x;
                Cs[row * 133 + c + 1] = acc2[mt][ntb][half * 2 + 1] + b2[c + 1] + yv.y;
            }
        }
    }
    __syncthreads();

    {
        int rl = tid & 127, cg = tid >> 7;   // 4 col-groups of 32
        int R = R0 + rl;
        int b = R / SPT, sp = R - b * SPT;
        size_t obase = (size_t)b * 128 * SPT + sp;
        #pragma unroll 8
        for (int j = 0; j < 32; j++) {
            int col = cg * 32 + j;
            out[obase + (size_t)col * SPT] = Cs[rl * 133 + col];
        }
    }
}

// =====================================================================
extern "C" void kernel_launch(void* const* d_in, const int* in_sizes, int n_in,
                              void* d_out, int out_size)
{
    const float* x    = (const float*)d_in[0];
    const float* bng  = (const float*)d_in[1];
    const float* bnb  = (const float*)d_in[2];
    const float* bnm  = (const float*)d_in[3];
    const float* bnv  = (const float*)d_in[4];
    const float* qkvw = (const float*)d_in[5];
    const float* qkvb = (const float*)d_in[6];
    const float* pw   = (const float*)d_in[7];
    const float* pb   = (const float*)d_in[8];
    const float* lng  = (const float*)d_in[9];
    const float* lnb  = (const float*)d_in[10];
    const float* w1   = (const float*)d_in[11];
    const float* b1   = (const float*)d_in[12];
    const float* w2   = (const float*)d_in[13];
    const float* b2   = (const float*)d_in[14];
    float* out = (float*)d_out;

    const int smem1 = (128 * PA + 64 * PA) * 2;
    const int smem2 = SM2_ELEMS * 2;
    const int smem4 = F4_TOTAL;

    cudaFuncSetAttribute(k1_qkv,      cudaFuncAttributeMaxDynamicSharedMemorySize, smem1);
    cudaFuncSetAttribute(k2_attnproj, cudaFuncAttributeMaxDynamicSharedMemorySize, smem2);
    cudaFuncSetAttribute(k4_ffn,      cudaFuncAttributeMaxDynamicSharedMemorySize, smem4);

    kprep       <<<768, 256>>>(qkvw, pw, w1, w2);
    k1_qkv      <<<MTOK / 128, 256, smem1>>>(x, bng, bnb, bnm, bnv, qkvb);
    k2_attnproj <<<NWIN, 256, smem2>>>(x, pb);
    k4_ffn      <<<MTOK / 128, 512, smem4>>>(lng, lnb, b1, b2, out);
}

// round 10
// speedup vs baseline: 1.2127x; 1.2127x over previous
#include <cuda_runtime.h>
#include <cuda_bf16.h>
#include <math.h>
#include <stdint.h>

// ---------------- problem constants ----------------
constexpr int CC   = 128;
constexpr int CT   = 16;
constexpr int CH   = 56;
constexpr int CW   = 56;
constexpr int NTOK = 196;
constexpr int NWIN = 1024;
constexpr int MTOK = NWIN * NTOK;     // 200704
constexpr int SPT  = CT * CH * CW;    // 50176
constexpr int HW   = CH * CW;         // 3136

// ---------------- scratch ----------------
__device__ float         g_y1 [(size_t)MTOK * 128];
__device__ __nv_bfloat16 g_wqkvT[384 * 128];
__device__ __nv_bfloat16 g_wpT  [128 * 128];
__device__ __nv_bfloat16 g_w1T  [512 * 128];
__device__ __nv_bfloat16 g_w2T  [128 * 512];

__device__ __forceinline__ void row_to_bsp(int R, int &b, int &sp) {
    int w = R / NTOK, n = R - w * NTOK;
    b = w >> 8;
    int rw = w & 255;
    int it = rw >> 6, ih = (rw >> 3) & 7, iw = rw & 7;
    int tt = n / 49;
    int rn = n - tt * 49;
    int hh = rn / 7, ww = rn - hh * 7;
    sp = (it * 4 + tt) * HW + (ih * 7 + hh) * CW + (iw * 7 + ww);
}

__device__ __forceinline__ void mma4(float* d, uint32_t a0, uint32_t a1, uint32_t a2, uint32_t a3,
                                     uint32_t b0, uint32_t b1) {
    asm volatile(
        "mma.sync.aligned.m16n8k16.row.col.f32.bf16.bf16.f32 "
        "{%0,%1,%2,%3},{%4,%5,%6,%7},{%8,%9},{%0,%1,%2,%3};"
        : "+f"(d[0]), "+f"(d[1]), "+f"(d[2]), "+f"(d[3])
        : "r"(a0), "r"(a1), "r"(a2), "r"(a3), "r"(b0), "r"(b1));
}

__device__ __forceinline__ void ldsm4(uint32_t* r, uint32_t saddr) {
    asm volatile("ldmatrix.sync.aligned.m8n8.x4.shared.b16 {%0,%1,%2,%3}, [%4];"
        : "=r"(r[0]), "=r"(r[1]), "=r"(r[2]), "=r"(r[3]) : "r"(saddr));
}

__device__ __forceinline__ uint32_t s2u(const void* p) {
    return (uint32_t)__cvta_generic_to_shared(p);
}

__device__ __forceinline__ uint32_t packbf(float x, float y) {
    __nv_bfloat162 t = __floats2bfloat162_rn(x, y);
    return *reinterpret_cast<uint32_t*>(&t);
}
__device__ __forceinline__ void st_bf2(__nv_bfloat16* p, float x, float y) {
    __nv_bfloat162 t = __floats2bfloat162_rn(x, y);
    *reinterpret_cast<__nv_bfloat162*>(p) = t;
}

constexpr int PA = 136;

// =====================================================================
// K0: weight transpose + bf16 convert
// =====================================================================
__global__ void kprep(const float* __restrict__ qkvw, const float* __restrict__ pw,
                      const float* __restrict__ w1,   const float* __restrict__ w2)
{
    int i = blockIdx.x * 256 + threadIdx.x;
    if (i < 49152) { int n = i >> 7, k = i & 127; g_wqkvT[n * 128 + k] = __float2bfloat16(qkvw[k * 384 + n]); return; }
    i -= 49152;
    if (i < 16384) { int n = i >> 7, k = i & 127; g_wpT[n * 128 + k] = __float2bfloat16(pw[k * 128 + n]); return; }
    i -= 16384;
    if (i < 65536) { int n = i >> 7, k = i & 127; g_w1T[n * 128 + k] = __float2bfloat16(w1[k * 512 + n]); return; }
    i -= 65536;
    if (i < 65536) { int n = i >> 9, k = i & 511; g_w2T[n * 512 + k] = __float2bfloat16(w2[k * 128 + n]); return; }
}

// =====================================================================
// K2f: fused BN+gather + qkv GEMM + attention (4 heads) + proj + residual.
// grid 1024 windows, 416 threads (13 warps = one per 16-row m-tile).
// =====================================================================
constexpr int PQ2 = 40;
constexpr int PVT = 216;
constexpr int PO  = 136;
// element offsets in dynamic smem (bf16)
constexpr int F_A = 0;                    // A [208][PA]        28288
constexpr int F_B = 28288;                // B [128][PA]        17408
constexpr int F_Q = F_B + 128 * PA;       // Qs [208][PQ2]       8320
constexpr int F_K = F_Q + 208 * PQ2;      // Ks [208][PQ2]       8320
constexpr int F_V = F_K + 208 * PQ2;      // Vt [32][PVT]        6912
constexpr int F_O = F_V + 32 * PVT;       // Os [208][PO]       28288
constexpr int F_ELEMS = F_O + 208 * PO;   // 97536 elems = 195072 B

__global__ __launch_bounds__(416) void k2_fused(
    const float* __restrict__ x,
    const float* __restrict__ bng, const float* __restrict__ bnb,
    const float* __restrict__ bnm, const float* __restrict__ bnv,
    const float* __restrict__ bq,  const float* __restrict__ bp)
{
    extern __shared__ unsigned char shraw[];
    __nv_bfloat16* sm = (__nv_bfloat16*)shraw;
    __nv_bfloat16* A  = sm + F_A;
    __nv_bfloat16* B  = sm + F_B;
    __nv_bfloat16* Qs = sm + F_Q;
    __nv_bfloat16* Ks = sm + F_K;
    __nv_bfloat16* Vt = sm + F_V;
    __nv_bfloat16* Os = sm + F_O;
    __shared__ float sc[128], sf[128];

    int tid = threadIdx.x, l = tid & 31, wid = tid >> 5;
    int win = blockIdx.x;
    int qbase = win * NTOK;
    int kq = (l & 3) * 2;
    const float scale = 0.17677669529663687f;

    if (tid < 128) {
        float s = bng[tid] * rsqrtf(bnv[tid] + 1e-5f);
        sc[tid] = s;
        sf[tid] = bnb[tid] - bnm[tid] * s;
    }
    // zero Os pad rows 196..207
    for (int i = tid; i < 12 * PO; i += 416) Os[196 * PO + i] = __float2bfloat16(0.f);
    __syncthreads();   // sc/sf ready

    // ---- gather + BN -> A (2 threads per row, 64 ch each) ----
    {
        int row = tid >> 1, seg = tid & 1;
        if (row < NTOK) {
            int b, sp; row_to_bsp(qbase + row, b, sp);
            const float* xp = x + (size_t)b * 128 * SPT + sp + (size_t)seg * 64 * SPT;
            #pragma unroll 8
            for (int j = 0; j < 64; j++) {
                int c = seg * 64 + j;
                A[row * PA + c] = __float2bfloat16(xp[(size_t)j * SPT] * sc[c] + sf[c]);
            }
        } else {
            for (int j = 0; j < 64; j++) A[row * PA + seg * 64 + j] = __float2bfloat16(0.f);
        }
    }

    int m0 = wid * 16;
    uint32_t sA = s2u(sm);
    uint32_t aA  = sA + (uint32_t)(((m0 + (l & 15)) * PA + (l >> 4) * 8) << 1);
    uint32_t aBg = sA + (uint32_t)((F_B + ((l & 7) + ((l >> 4) << 3)) * PA + ((l >> 3) & 1) * 8) << 1);
    uint32_t aQ  = sA + (uint32_t)((F_Q + (m0 + (l & 15)) * PQ2 + (l >> 4) * 8) << 1);
    uint32_t aKb = sA + (uint32_t)((F_K + ((l & 7) + ((l >> 4) << 3)) * PQ2 + ((l >> 3) & 1) * 8) << 1);
    uint32_t aVb = sA + (uint32_t)((F_V + ((l & 7) + ((l >> 4) << 3)) * PVT + ((l >> 3) & 1) * 8) << 1);
    uint32_t aO  = sA + (uint32_t)((F_O + (m0 + (l & 15)) * PO + (l >> 4) * 8) << 1);
    uint32_t aBO = sA + (uint32_t)((F_O + (m0 + (l & 15)) * PO + (l >> 4) * 8) << 1); (void)aBO;

    int qr0 = m0 + (l >> 2), qr1 = qr0 + 8;

    for (int h = 0; h < 4; h++) {
        int coff = h * 32;
        // load the 96 weight rows for this head (Q|K|V slices of wqkvT)
        for (int i = tid; i < 96 * 16; i += 416) {
            int n = i >> 4, seg = i & 15;
            int src_row = (n < 32) ? (coff + n) : (n < 64) ? (128 + coff + n - 32) : (256 + coff + n - 64);
            *(uint4*)&B[n * PA + seg * 8] = *(const uint4*)&g_wqkvT[src_row * 128 + seg * 8];
        }
        __syncthreads();   // B ready; prev head's attention done (QKV writable)

        // qkv gemm: warp computes its 16 rows x 96 cols
        {
            float acc[12][4];
            #pragma unroll
            for (int t = 0; t < 12; t++) acc[t][0] = acc[t][1] = acc[t][2] = acc[t][3] = 0.f;
            #pragma unroll
            for (int k0 = 0; k0 < 128; k0 += 16) {
                uint32_t a[4];
                ldsm4(a, aA + k0 * 2);
                #pragma unroll
                for (int p = 0; p < 6; p++) {
                    uint32_t bb[4];
                    ldsm4(bb, aBg + (p * 16 * PA + k0) * 2);
                    mma4(acc[2 * p],     a[0], a[1], a[2], a[3], bb[0], bb[1]);
                    mma4(acc[2 * p + 1], a[0], a[1], a[2], a[3], bb[2], bb[3]);
                }
            }
            #pragma unroll
            for (int nt = 0; nt < 12; nt++) {
                int blk = nt >> 2;
                int c = (nt & 3) * 8 + kq;
                float bx = bq[blk * 128 + coff + c];
                float by = bq[blk * 128 + coff + c + 1];
                float v00 = acc[nt][0] + bx, v01 = acc[nt][1] + by;
                float v10 = acc[nt][2] + bx, v11 = acc[nt][3] + by;
                if (blk == 0) {
                    st_bf2(&Qs[qr0 * PQ2 + c], v00, v01);
                    st_bf2(&Qs[qr1 * PQ2 + c], v10, v11);
                } else if (blk == 1) {
                    st_bf2(&Ks[qr0 * PQ2 + c], v00, v01);
                    st_bf2(&Ks[qr1 * PQ2 + c], v10, v11);
                } else {
                    Vt[c * PVT + qr0]       = __float2bfloat16(v00);
                    Vt[(c + 1) * PVT + qr0] = __float2bfloat16(v01);
                    Vt[c * PVT + qr1]       = __float2bfloat16(v10);
                    Vt[(c + 1) * PVT + qr1] = __float2bfloat16(v11);
                }
            }
        }
        __syncthreads();   // Q/K/Vt ready

        // attention: one m-tile per warp
        {
            float S[26][4];
            #pragma unroll
            for (int t = 0; t < 26; t++) S[t][0] = S[t][1] = S[t][2] = S[t][3] = 0.f;

            #pragma unroll
            for (int k0 = 0; k0 < 32; k0 += 16) {
                uint32_t aq[4];
                ldsm4(aq, aQ + k0 * 2);
                #pragma unroll
                for (int p = 0; p < 13; p++) {
                    uint32_t bk[4];
                    ldsm4(bk, aKb + (p * 16 * PQ2 + k0) * 2);
                    mma4(S[2 * p],     aq[0], aq[1], aq[2], aq[3], bk[0], bk[1]);
                    mma4(S[2 * p + 1], aq[0], aq[1], aq[2], aq[3], bk[2], bk[3]);
                }
            }

            float mx0 = -1e30f, mx1 = -1e30f;
            #pragma unroll
            for (int t = 0; t < 26; t++) {
                int c = t * 8 + kq;
                if (c < NTOK)     { mx0 = fmaxf(mx0, S[t][0]); mx1 = fmaxf(mx1, S[t][2]); }
                if (c + 1 < NTOK) { mx0 = fmaxf(mx0, S[t][1]); mx1 = fmaxf(mx1, S[t][3]); }
            }
            mx0 = fmaxf(mx0, __shfl_xor_sync(0xffffffffu, mx0, 1));
            mx0 = fmaxf(mx0, __shfl_xor_sync(0xffffffffu, mx0, 2));
            mx1 = fmaxf(mx1, __shfl_xor_sync(0xffffffffu, mx1, 1));
            mx1 = fmaxf(mx1, __shfl_xor_sync(0xffffffffu, mx1, 2));

            float s0 = 0.f, s1 = 0.f;
            #pragma unroll
            for (int t = 0; t < 26; t++) {
                int c = t * 8 + kq;
                if (c < NTOK)     { S[t][0] = __expf(scale * (S[t][0] - mx0)); s0 += S[t][0];
                                    S[t][2] = __expf(scale * (S[t][2] - mx1)); s1 += S[t][2]; }
                else              { S[t][0] = 0.f; S[t][2] = 0.f; }
                if (c + 1 < NTOK) { S[t][1] = __expf(scale * (S[t][1] - mx0)); s0 += S[t][1];
                                    S[t][3] = __expf(scale * (S[t][3] - mx1)); s1 += S[t][3]; }
                else              { S[t][1] = 0.f; S[t][3] = 0.f; }
            }
            s0 += __shfl_xor_sync(0xffffffffu, s0, 1);
            s0 += __shfl_xor_sync(0xffffffffu, s0, 2);
            s1 += __shfl_xor_sync(0xffffffffu, s1, 1);
            s1 += __shfl_xor_sync(0xffffffffu, s1, 2);
            float i0 = 1.f / s0, i1 = 1.f / s1;
            #pragma unroll
            for (int t = 0; t < 26; t++) {
                S[t][0] *= i0; S[t][1] *= i0; S[t][2] *= i1; S[t][3] *= i1;
            }

            float O[4][4];
            #pragma unroll
            for (int nt = 0; nt < 4; nt++) O[nt][0] = O[nt][1] = O[nt][2] = O[nt][3] = 0.f;
            #pragma unroll
            for (int kt = 0; kt < 13; kt++) {
                uint32_t pa0 = packbf(S[2 * kt][0],     S[2 * kt][1]);
                uint32_t pa1 = packbf(S[2 * kt][2],     S[2 * kt][3]);
                uint32_t pa2 = packbf(S[2 * kt + 1][0], S[2 * kt + 1][1]);
                uint32_t pa3 = packbf(S[2 * kt + 1][2], S[2 * kt + 1][3]);
                #pragma unroll
                for (int p = 0; p < 2; p++) {
                    uint32_t bv[4];
                    ldsm4(bv, aVb + (p * 16 * PVT + kt * 16) * 2);
                    mma4(O[2 * p],     pa0, pa1, pa2, pa3, bv[0], bv[1]);
                    mma4(O[2 * p + 1], pa0, pa1, pa2, pa3, bv[2], bv[3]);
                }
            }

            #pragma unroll
            for (int nt = 0; nt < 4; nt++) {
                int cd = coff + nt * 8 + kq;
                if (qr0 < NTOK) st_bf2(&Os[qr0 * PO + cd], O[nt][0], O[nt][1]);
                if (qr1 < NTOK) st_bf2(&Os[qr1 * PO + cd], O[nt][2], O[nt][3]);
            }
        }
    }

    // ---- proj phase ----
    for (int i = tid; i < 128 * 16; i += 416) {
        int n = i >> 4, seg = i & 15;
        *(uint4*)&B[n * PA + seg * 8] = *(const uint4*)&g_wpT[n * 128 + seg * 8];
    }
    __syncthreads();   // wp in B; Os complete

    {
        float acc[16][4];
        #pragma unroll
        for (int t = 0; t < 16; t++) acc[t][0] = acc[t][1] = acc[t][2] = acc[t][3] = 0.f;
        #pragma unroll
        for (int k0 = 0; k0 < 128; k0 += 16) {
            uint32_t ao[4];
            ldsm4(ao, aO + k0 * 2);
            #pragma unroll
            for (int p = 0; p < 8; p++) {
                uint32_t bb[4];
                ldsm4(bb, aBg + (p * 16 * PA + k0) * 2);
                mma4(acc[2 * p],     ao[0], ao[1], ao[2], ao[3], bb[0], bb[1]);
                mma4(acc[2 * p + 1], ao[0], ao[1], ao[2], ao[3], bb[2], bb[3]);
            }
        }
        #pragma unroll
        for (int half = 0; half < 2; half++) {
            int row = m0 + (l >> 2) + half * 8;
            if (row < NTOK) {
                int b, sp; row_to_bsp(qbase + row, b, sp);
                size_t xb = (size_t)b * 128 * SPT + sp;
                size_t tok = (size_t)b * SPT + sp;
                #pragma unroll
                for (int ntb = 0; ntb < 16; ntb++) {
                    int cg = ntb * 8 + kq;
                    float2 o;
                    o.x = acc[ntb][half * 2 + 0] + bp[cg]     + x[xb + (size_t)cg * SPT];
                    o.y = acc[ntb][half * 2 + 1] + bp[cg + 1] + x[xb + (size_t)(cg + 1) * SPT];
                    *(float2*)&g_y1[tok * 128 + cg] = o;
                }
            }
        }
    }
}

// =====================================================================
// K4: fused LN + fc1 + GELU + fc2 + residual + transposed output.
// (R7 passing version: 256 thr, 3x 128*PA smem tiles, 2 CTA/SM)
// =====================================================================
constexpr int OFF_H4 = 128 * PA;
constexpr int OFF_B4 = 2 * 128 * PA;
constexpr int SM4_ELEMS = 3 * 128 * PA;

__global__ __launch_bounds__(256) void k4_ffn(
    const float* __restrict__ lng, const float* __restrict__ lnb,
    const float* __restrict__ b1,  const float* __restrict__ b2,
    float* __restrict__ out)
{
    extern __shared__ unsigned char shraw[];
    __nv_bfloat16* As = (__nv_bfloat16*)shraw;
    __nv_bfloat16* H  = As + OFF_H4;
    __nv_bfloat16* Bs = As + OFF_B4;
    int tid = threadIdx.x, l = tid & 31, w = tid >> 5;
    int R0 = blockIdx.x * 128;

    // LN -> As (bf16)
    {
        int row = tid >> 1, seg = tid & 1;
        const float* src = &g_y1[(size_t)(R0 + row) * 128 + seg * 64];
        float s1 = 0.f, s2 = 0.f;
        #pragma unroll
        for (int j = 0; j < 64; j += 4) {
            float4 t = *(const float4*)&src[j];
            s1 += t.x + t.y + t.z + t.w;
            s2 += t.x * t.x + t.y * t.y + t.z * t.z + t.w * t.w;
        }
        s1 += __shfl_xor_sync(0xffffffffu, s1, 1);
        s2 += __shfl_xor_sync(0xffffffffu, s2, 1);
        float mean = s1 * (1.f / 128.f);
        float var  = s2 * (1.f / 128.f) - mean * mean;
        float rstd = rsqrtf(var + 1e-5f);
        #pragma unroll
        for (int j = 0; j < 64; j += 2) {
            int c = seg * 64 + j;
            float v0 = (src[j]     - mean) * rstd * lng[c]     + lnb[c];
            float v1 = (src[j + 1] - mean) * rstd * lng[c + 1] + lnb[c + 1];
            *(uint32_t*)&As[row * PA + c] = packbf(v0, v1);
        }
    }

    int mw = (w >> 1) * 32, nw = (w & 1) * 32;
    int kq = (l & 3) * 2;

    uint32_t aA4 = s2u(As) + (((mw + (l & 15)) * PA + (l >> 4) * 8) << 1);
    uint32_t aH4 = s2u(H)  + (((mw + (l & 15)) * PA + (l >> 4) * 8) << 1);
    uint32_t bB4 = s2u(Bs) + ((((l & 7) + ((l >> 4) << 3)) * PA + ((l >> 3) & 1) * 8) << 1);

    float acc2[2][2][4][4];
    #pragma unroll
    for (int a = 0; a < 2; a++)
        #pragma unroll
        for (int t = 0; t < 2; t++)
            #pragma unroll
            for (int bb = 0; bb < 4; bb++)
                acc2[a][t][bb][0] = acc2[a][t][bb][1] = acc2[a][t][bb][2] = acc2[a][t][bb][3] = 0.f;

    for (int kc = 0; kc < 4; kc++) {
        __syncthreads();
        for (int i = tid; i < 128 * 16; i += 256) {
            int n = i >> 4, seg = i & 15;
            *(uint4*)&Bs[n * PA + seg * 8] = *(const uint4*)&g_w1T[(size_t)(kc * 128 + n) * 128 + seg * 8];
        }
        __syncthreads();

        // fc1 + GELU -> H
        #pragma unroll
        for (int nt = 0; nt < 2; nt++) {
            float acc[2][4][4];
            #pragma unroll
            for (int a = 0; a < 2; a++)
                #pragma unroll
                for (int bb = 0; bb < 4; bb++)
                    acc[a][bb][0] = acc[a][bb][1] = acc[a][bb][2] = acc[a][bb][3] = 0.f;

            #pragma unroll
            for (int k0 = 0; k0 < 128; k0 += 16) {
                uint32_t a0[4], a1[4], b0[4], b1[4];
                ldsm4(a0, aA4 + k0 * 2);
                ldsm4(a1, aA4 + 16 * PA * 2 + k0 * 2);
                ldsm4(b0, bB4 + ((nt * 64 + nw) * PA + k0) * 2);
                ldsm4(b1, bB4 + ((nt * 64 + nw + 16) * PA + k0) * 2);
                mma4(acc[0][0], a0[0], a0[1], a0[2], a0[3], b0[0], b0[1]);
                mma4(acc[0][1], a0[0], a0[1], a0[2], a0[3], b0[2], b0[3]);
                mma4(acc[0][2], a0[0], a0[1], a0[2], a0[3], b1[0], b1[1]);
                mma4(acc[0][3], a0[0], a0[1], a0[2], a0[3], b1[2], b1[3]);
                mma4(acc[1][0], a1[0], a1[1], a1[2], a1[3], b0[0], b0[1]);
                mma4(acc[1][1], a1[0], a1[1], a1[2], a1[3], b0[2], b0[3]);
                mma4(acc[1][2], a1[0], a1[1], a1[2], a1[3], b1[0], b1[1]);
                mma4(acc[1][3], a1[0], a1[1], a1[2], a1[3], b1[2], b1[3]);
            }
            #pragma unroll
            for (int ntb = 0; ntb < 4; ntb++) {
                int cl = nt * 64 + nw + ntb * 8 + kq;
                float bx = b1[kc * 128 + cl], by = b1[kc * 128 + cl + 1];
                #pragma unroll
                for (int mt = 0; mt < 2; mt++) {
                    #pragma unroll
                    for (int half = 0; half < 2; half++) {
                        int row = mw + mt * 16 + (l >> 2) + half * 8;
                        float h0 = acc[mt][ntb][half * 2 + 0] + bx;
                        float h1 = acc[mt][ntb][half * 2 + 1] + by;
                        float g0 = 0.5f * h0 * (1.f + erff(h0 * 0.70710678118654752f));
                        float g1 = 0.5f * h1 * (1.f + erff(h1 * 0.70710678118654752f));
                        st_bf2(&H[row * PA + cl], g0, g1);
                    }
                }
            }
        }
        __syncthreads();
        for (int i = tid; i < 128 * 16; i += 256) {
            int n = i >> 4, seg = i & 15;
            *(uint4*)&Bs[n * PA + seg * 8] = *(const uint4*)&g_w2T[(size_t)n * 512 + kc * 128 + seg * 8];
        }
        __syncthreads();
        // fc2 accumulate
        #pragma unroll
        for (int k0 = 0; k0 < 128; k0 += 16) {
            uint32_t a0[4], a1[4];
            ldsm4(a0, aH4 + k0 * 2);
            ldsm4(a1, aH4 + 16 * PA * 2 + k0 * 2);
            #pragma unroll
            for (int t = 0; t < 2; t++) {
                uint32_t b0[4], b1[4];
                ldsm4(b0, bB4 + ((t * 64 + nw) * PA + k0) * 2);
                ldsm4(b1, bB4 + ((t * 64 + nw + 16) * PA + k0) * 2);
                mma4(acc2[0][t][0], a0[0], a0[1], a0[2], a0[3], b0[0], b0[1]);
                mma4(acc2[0][t][1], a0[0], a0[1], a0[2], a0[3], b0[2], b0[3]);
                mma4(acc2[0][t][2], a0[0], a0[1], a0[2], a0[3], b1[0], b1[1]);
                mma4(acc2[0][t][3], a0[0], a0[1], a0[2], a0[3], b1[2], b1[3]);
                mma4(acc2[1][t][0], a1[0], a1[1], a1[2], a1[3], b0[0], b0[1]);
                mma4(acc2[1][t][1], a1[0], a1[1], a1[2], a1[3], b0[2], b0[3]);
                mma4(acc2[1][t][2], a1[0], a1[1], a1[2], a1[3], b1[0], b1[1]);
                mma4(acc2[1][t][3], a1[0], a1[1], a1[2], a1[3], b1[2], b1[3]);
            }
        }
    }

    __syncthreads();
    float* Cs = (float*)shraw;   // [128][133]
    #pragma unroll
    for (int mt = 0; mt < 2; mt++) {
        #pragma unroll
        for (int half = 0; half < 2; half++) {
            int row = mw + mt * 16 + (l >> 2) + half * 8;
            #pragma unroll
            for (int t = 0; t < 2; t++) {
                #pragma unroll
                for (int ntb = 0; ntb < 4; ntb++) {
                    int c = t * 64 + nw + ntb * 8 + kq;
                    float2 yv = *(const float2*)&g_y1[(size_t)(R0 + row) * 128 + c];
                    Cs[row * 133 + c]     = acc2[mt][t][ntb][half * 2 + 0] + b2[c]     + yv.x;
                    Cs[row * 133 + c + 1] = acc2[mt][t][ntb][half * 2 + 1] + b2[c + 1] + yv.y;
                }
            }
        }
    }
    __syncthreads();

    int rl = tid & 127, cg = tid >> 7;
    int R = R0 + rl;
    int b = R / SPT, sp = R - b * SPT;
    size_t obase = (size_t)b * 128 * SPT + sp;
    #pragma unroll 8
    for (int j = 0; j < 64; j++) {
        int col = cg * 64 + j;
        out[obase + (size_t)col * SPT] = Cs[rl * 133 + col];
    }
}

// =====================================================================
extern "C" void kernel_launch(void* const* d_in, const int* in_sizes, int n_in,
                              void* d_out, int out_size)
{
    const float* x    = (const float*)d_in[0];
    const float* bng  = (const float*)d_in[1];
    const float* bnb  = (const float*)d_in[2];
    const float* bnm  = (const float*)d_in[3];
    const float* bnv  = (const float*)d_in[4];
    const float* qkvw = (const float*)d_in[5];
    const float* qkvb = (const float*)d_in[6];
    const float* pw   = (const float*)d_in[7];
    const float* pb   = (const float*)d_in[8];
    const float* lng  = (const float*)d_in[9];
    const float* lnb  = (const float*)d_in[10];
    const float* w1   = (const float*)d_in[11];
    const float* b1   = (const float*)d_in[12];
    const float* w2   = (const float*)d_in[13];
    const float* b2   = (const float*)d_in[14];
    float* out = (float*)d_out;

    const int smem2 = F_ELEMS * 2;       // 195072
    const int smem4 = SM4_ELEMS * 2;     // 104448

    cudaFuncSetAttribute(k2_fused, cudaFuncAttributeMaxDynamicSharedMemorySize, smem2);
    cudaFuncSetAttribute(k4_ffn,   cudaFuncAttributeMaxDynamicSharedMemorySize, smem4);

    kprep    <<<768, 256>>>(qkvw, pw, w1, w2);
    k2_fused <<<NWIN, 416, smem2>>>(x, bng, bnb, bnm, bnv, qkvb, pb);
    k4_ffn   <<<MTOK / 128, 256, smem4>>>(lng, lnb, b1, b2, out);
}